// round 1
// baseline (speedup 1.0000x reference)
#include <cuda_runtime.h>
#include <math.h>

#define B  32
#define S  2048
#define D  64
#define R  4
#define NB 32
#define BL 64
#define W  128   // 2*BL

// ---------------- scratch (device globals; no allocation) ----------------
__device__ int   g_bucket[B*R*S];            // 1 MB
__device__ int   g_sortidx[B*R*S];           // 1 MB
__device__ float g_qninv[B*S];               // 256 KB
__device__ float g_att[(size_t)B*S*R*D];     // 64 MB  [b][t][r][d]
__device__ float g_lse[B*S*R];               // 1 MB   [b][t][r]

// ---------------- kernel 1: hash projection + bucket + key norm ----------
__global__ void hash_kernel(const float* __restrict__ query,
                            const float* __restrict__ randm)
{
    __shared__ float sR[D*64];                // rand[b]: d-major, rk = r*16+k
    const int b   = blockIdx.y;
    const int tid = threadIdx.x;
    for (int idx = tid; idx < D*64; idx += 128)
        sR[idx] = randm[b*D*64 + idx];
    __syncthreads();

    const int t = blockIdx.x*128 + tid;
    const float* q = query + ((size_t)b*S + t)*D;

    float acc[64];
#pragma unroll
    for (int i = 0; i < 64; i++) acc[i] = 0.f;
    float nrm = 0.f;
    for (int d = 0; d < D; d++) {
        float qd = q[d];
        nrm += qd*qd;
        const float* rr = &sR[d*64];
#pragma unroll
        for (int i = 0; i < 64; i++) acc[i] += qd * rr[i];
    }
    g_qninv[b*S + t] = rsqrtf(fmaxf(nrm, 1e-12f));

#pragma unroll
    for (int r = 0; r < R; r++) {
        float bv = acc[r*16];
        int   bi = 0;
#pragma unroll
        for (int k = 1; k < 16; k++) {
            float v = acc[r*16 + k];
            if (v > bv) { bv = v; bi = k; }
        }
#pragma unroll
        for (int k = 0; k < 16; k++) {
            float v = -acc[r*16 + k];
            if (v > bv) { bv = v; bi = 16 + k; }
        }
        g_bucket[(b*R + r)*S + t] = bi;
    }
}

// ---------------- kernel 2: stable counting sort per (b, r) --------------
__global__ void sort_kernel()
{
    __shared__ int hist[NB*256];   // bucket-major, thread-minor
    __shared__ int partials[256];
    const int br  = blockIdx.x;
    const int tid = threadIdx.x;
    const int* bk = g_bucket  + br*S;
    int*     sidx = g_sortidx + br*S;

    for (int i = tid; i < NB*256; i += 256) hist[i] = 0;
    __syncthreads();

    const int base = tid*8;
    int myb[8];
#pragma unroll
    for (int k = 0; k < 8; k++) { myb[k] = bk[base + k]; hist[myb[k]*256 + tid]++; }
    __syncthreads();

    // exclusive scan over 8192 entries in index order (stable)
    int run = 0;
    for (int i = tid*32; i < tid*32 + 32; i++) { int v = hist[i]; hist[i] = run; run += v; }
    partials[tid] = run;
    __syncthreads();
    if (tid == 0) {
        int s = 0;
        for (int i = 0; i < 256; i++) { int v = partials[i]; partials[i] = s; s += v; }
    }
    __syncthreads();
    const int add = partials[tid];
    for (int i = tid*32; i < tid*32 + 32; i++) hist[i] += add;
    __syncthreads();

#pragma unroll
    for (int k = 0; k < 8; k++) {
        int bb  = myb[k];
        int rnk = hist[bb*256 + tid]++;
        sidx[rnk] = base + k;
    }
}

// ---------------- kernel 3: bucketed attention (one block per b,bucket) --
// dynamic smem layout (bytes):
//   [0,2048)       kiS    : int[512]      window key positions, per round
//   [2048,4096)    countf : float[512]    duplicate counts
//   [4096,20480)   qs     : float[64*64]  Q tile (row-major, stride 64)
//   [20480,53504)  ksT    : float[64*129] K^T tile (d-major, pad 129)
//                  (aliased by ps float[64*128] and cnt int[2048])
//   [53504,86272)  vs     : float[128*64] V tile
#define ATTN_SMEM 86272

__global__ void __launch_bounds__(256) attn_kernel(const float* __restrict__ query,
                                                   const float* __restrict__ value)
{
    extern __shared__ char smem[];
    int*   kiS    = (int*)  smem;
    float* countf = (float*)(smem + 2048);
    float* qs     = (float*)(smem + 4096);
    float* ksT    = (float*)(smem + 20480);
    float* ps     = ksT;                  // alias (after GEMM1)
    int*   cnt    = (int*)  ksT;          // alias (phase 0 only)
    float* vs     = (float*)(smem + 53504);

    const int blk = blockIdx.x;
    const int b   = blk >> 5;
    const int n   = blk & 31;
    const int tid = threadIdx.x;
    const int tx  = tid & 31;
    const int ty  = tid >> 5;

    const int* sidx_b = g_sortidx + b*R*S;
    const int  prev   = (n + 31) & 31;

    // phase 0: window key positions + multiplicity counts (all rounds)
    for (int idx = tid; idx < 512; idx += 256) {
        int r = idx >> 7, j = idx & 127;
        int slot = (j < 64) ? (prev*64 + j) : (n*64 + j - 64);
        kiS[idx] = sidx_b[r*S + slot];
    }
    for (int idx = tid; idx < 2048; idx += 256) cnt[idx] = 0;
    __syncthreads();
    for (int idx = tid; idx < 512; idx += 256) atomicAdd(&cnt[kiS[idx]], 1);
    __syncthreads();
    for (int idx = tid; idx < 512; idx += 256) countf[idx] = (float)cnt[kiS[idx]];
    __syncthreads();

    const float* Q  = query + (size_t)b*S*D;
    const float* V  = value + (size_t)b*S*D;
    const float* qn = g_qninv + b*S;

    for (int r = 0; r < R; r++) {
        // ---- load tiles ----
        for (int idx = tid; idx < 4096; idx += 256) {
            int i = idx >> 6, d = idx & 63;
            qs[idx] = Q[(size_t)kiS[r*128 + 64 + i]*D + d];
        }
        for (int idx = tid; idx < 8192; idx += 256) {
            int j = idx >> 6, d = idx & 63;
            int kp = kiS[r*128 + j];
            ksT[d*129 + j] = Q[(size_t)kp*D + d] * qn[kp];
        }
        for (int idx = tid; idx < 8192; idx += 256) {
            int j = idx >> 6, d = idx & 63;
            vs[idx] = V[(size_t)kiS[r*128 + j]*D + d];
        }
        __syncthreads();

        // ---- GEMM1: qk[i][j], thread tile 8 rows x 4 cols ----
        float acc[8][4];
#pragma unroll
        for (int ii = 0; ii < 8; ii++)
#pragma unroll
            for (int jj = 0; jj < 4; jj++) acc[ii][jj] = 0.f;

        for (int d0 = 0; d0 < 64; d0 += 2) {
            float ka[4], kb[4];
#pragma unroll
            for (int jj = 0; jj < 4; jj++) {
                ka[jj] = ksT[ d0   *129 + tx + 32*jj];
                kb[jj] = ksT[(d0+1)*129 + tx + 32*jj];
            }
#pragma unroll
            for (int ii = 0; ii < 8; ii++) {
                float2 q2 = *(const float2*)&qs[(ty + 8*ii)*64 + d0];
#pragma unroll
                for (int jj = 0; jj < 4; jj++)
                    acc[ii][jj] += q2.x*ka[jj] + q2.y*kb[jj];
            }
        }
        __syncthreads();   // ksT reads done; safe to overwrite via ps alias

        // ---- masks + softmax/lse (row fully within one warp) ----
        int kp4[4];
#pragma unroll
        for (int jj = 0; jj < 4; jj++) kp4[jj] = kiS[r*128 + tx + 32*jj];

#pragma unroll
        for (int ii = 0; ii < 8; ii++) {
            int   i    = ty + 8*ii;
            int   qpos = kiS[r*128 + 64 + i];
            float vr[4];
            float m = -3.4e38f;
#pragma unroll
            for (int jj = 0; jj < 4; jj++) {
                float v = acc[ii][jj] * 0.125f;
                int   kp = kp4[jj];
                if      (qpos <  kp) v = -1.0e9f;
                else if (qpos == kp) v = -1.0e5f;
                vr[jj] = v;
                m = fmaxf(m, v);
            }
#pragma unroll
            for (int off = 16; off; off >>= 1)
                m = fmaxf(m, __shfl_xor_sync(0xffffffffu, m, off));
            float ssum = 0.f;
#pragma unroll
            for (int jj = 0; jj < 4; jj++) { vr[jj] = __expf(vr[jj] - m); ssum += vr[jj]; }
#pragma unroll
            for (int off = 16; off; off >>= 1)
                ssum += __shfl_xor_sync(0xffffffffu, ssum, off);
            float inv = 1.f / ssum;
#pragma unroll
            for (int jj = 0; jj < 4; jj++) {
                int j = tx + 32*jj;
                ps[i*128 + j] = vr[jj] * inv / countf[r*128 + j];
            }
            if (tx == 0)
                g_lse[((size_t)b*S + qpos)*R + r] = m + __logf(ssum);
        }
        __syncthreads();

        // ---- GEMM2: out[i][d] = sum_j p[i][j]*v[j][d], tile 8 rows x 2 cols ----
        float acc2[8][2];
#pragma unroll
        for (int ii = 0; ii < 8; ii++) { acc2[ii][0] = 0.f; acc2[ii][1] = 0.f; }

        for (int j0 = 0; j0 < 128; j0 += 2) {
            float va0 = vs[ j0   *64 + tx], va1 = vs[ j0   *64 + tx + 32];
            float vb0 = vs[(j0+1)*64 + tx], vb1 = vs[(j0+1)*64 + tx + 32];
#pragma unroll
            for (int ii = 0; ii < 8; ii++) {
                float2 p2 = *(const float2*)&ps[(ty + 8*ii)*128 + j0];
                acc2[ii][0] += p2.x*va0 + p2.y*vb0;
                acc2[ii][1] += p2.x*va1 + p2.y*vb1;
            }
        }

#pragma unroll
        for (int ii = 0; ii < 8; ii++) {
            int i    = ty + 8*ii;
            int qpos = kiS[r*128 + 64 + i];
            float* o = g_att + (((size_t)b*S + qpos)*R + r)*D;
            o[tx]      = acc2[ii][0];
            o[tx + 32] = acc2[ii][1];
        }
        __syncthreads();   // before next round overwrites tiles
    }
}

// ---------------- kernel 4: per-position round combine -------------------
__global__ void combine_kernel(float* __restrict__ out)
{
    const int tid = threadIdx.x;
    const int d   = tid & 63;
    const int row = (blockIdx.x << 2) + (tid >> 6);   // b*S + t
    const float* l = g_lse + (size_t)row*R;
    float l0 = l[0], l1 = l[1], l2 = l[2], l3 = l[3];
    float m  = fmaxf(fmaxf(l0, l1), fmaxf(l2, l3));
    float w0 = __expf(l0 - m), w1 = __expf(l1 - m);
    float w2 = __expf(l2 - m), w3 = __expf(l3 - m);
    float inv = 1.f / (w0 + w1 + w2 + w3);
    const float* a = g_att + (size_t)row*R*D;
    out[(size_t)row*D + d] =
        (a[0*D + d]*w0 + a[1*D + d]*w1 + a[2*D + d]*w2 + a[3*D + d]*w3) * inv;
}

// ---------------- launch --------------------------------------------------
extern "C" void kernel_launch(void* const* d_in, const int* in_sizes, int n_in,
                              void* d_out, int out_size)
{
    const float* query = (const float*)d_in[0];
    const float* value = (const float*)d_in[1];
    const float* randm = (const float*)d_in[2];
    float* out = (float*)d_out;

    cudaFuncSetAttribute(attn_kernel,
                         cudaFuncAttributeMaxDynamicSharedMemorySize, ATTN_SMEM);

    hash_kernel<<<dim3(S/128, B), 128>>>(query, randm);
    sort_kernel<<<B*R, 256>>>();
    attn_kernel<<<B*NB, 256, ATTN_SMEM>>>(query, value);
    combine_kernel<<<(B*S)/4, 256>>>(out);
}

// round 2
// speedup vs baseline: 2.8199x; 2.8199x over previous
#include <cuda_runtime.h>
#include <math.h>

#define B  32
#define S  2048
#define D  64
#define R  4
#define NB 32
#define BL 64
#define W  128   // 2*BL

// ---------------- scratch (device globals; no allocation) ----------------
__device__ int   g_bucket[B*R*S];            // 1 MB
__device__ int   g_sortidx[B*R*S];           // 1 MB
__device__ float g_qninv[B*S];               // 256 KB
__device__ float g_att[(size_t)B*S*R*D];     // 64 MB  [b][t][r][d]
__device__ float g_lse[B*S*R];               // 1 MB   [b][t][r]

// ---------------- tf32 helpers -------------------------------------------
__device__ __forceinline__ unsigned f2tf(float f) {
    unsigned u;
    asm("cvt.rna.tf32.f32 %0, %1;" : "=r"(u) : "f"(f));
    return u;
}
__device__ __forceinline__ float tff(float f) { return __uint_as_float(f2tf(f)); }

__device__ __forceinline__ void mma_tf32(float* c,
                                         unsigned a0, unsigned a1, unsigned a2, unsigned a3,
                                         unsigned b0, unsigned b1)
{
    asm volatile(
        "mma.sync.aligned.m16n8k8.row.col.f32.tf32.tf32.f32 "
        "{%0,%1,%2,%3}, {%4,%5,%6,%7}, {%8,%9}, {%0,%1,%2,%3};"
        : "+f"(c[0]), "+f"(c[1]), "+f"(c[2]), "+f"(c[3])
        : "r"(a0), "r"(a1), "r"(a2), "r"(a3), "r"(b0), "r"(b1));
}

// ---------------- kernel 1: hash projection + bucket + key norm ----------
__global__ void hash_kernel(const float* __restrict__ query,
                            const float* __restrict__ randm)
{
    __shared__ float sR[D*64];                // rand[b]: d-major, rk = r*16+k
    const int b   = blockIdx.y;
    const int tid = threadIdx.x;
    for (int idx = tid; idx < D*64; idx += 128)
        sR[idx] = randm[b*D*64 + idx];
    __syncthreads();

    const int t = blockIdx.x*128 + tid;
    const float* q = query + ((size_t)b*S + t)*D;

    float acc[64];
#pragma unroll
    for (int i = 0; i < 64; i++) acc[i] = 0.f;
    float nrm = 0.f;
    for (int d = 0; d < D; d++) {
        float qd = q[d];
        nrm += qd*qd;
        const float* rr = &sR[d*64];
#pragma unroll
        for (int i = 0; i < 64; i++) acc[i] += qd * rr[i];
    }
    g_qninv[b*S + t] = rsqrtf(fmaxf(nrm, 1e-12f));

#pragma unroll
    for (int r = 0; r < R; r++) {
        float bv = acc[r*16];
        int   bi = 0;
#pragma unroll
        for (int k = 1; k < 16; k++) {
            float v = acc[r*16 + k];
            if (v > bv) { bv = v; bi = k; }
        }
#pragma unroll
        for (int k = 0; k < 16; k++) {
            float v = -acc[r*16 + k];
            if (v > bv) { bv = v; bi = 16 + k; }
        }
        g_bucket[(b*R + r)*S + t] = bi;
    }
}

// ---------------- kernel 2: stable counting sort per (b, r) --------------
__global__ void sort_kernel()
{
    __shared__ int hist[NB*256];   // bucket-major, thread-minor
    __shared__ int partials[256];
    const int br  = blockIdx.x;
    const int tid = threadIdx.x;
    const int* bk = g_bucket  + br*S;
    int*     sidx = g_sortidx + br*S;

    for (int i = tid; i < NB*256; i += 256) hist[i] = 0;
    __syncthreads();

    const int base = tid*8;
    int myb[8];
#pragma unroll
    for (int k = 0; k < 8; k++) { myb[k] = bk[base + k]; hist[myb[k]*256 + tid]++; }
    __syncthreads();

    int run = 0;
    for (int i = tid*32; i < tid*32 + 32; i++) { int v = hist[i]; hist[i] = run; run += v; }
    partials[tid] = run;
    __syncthreads();
    if (tid == 0) {
        int s = 0;
        for (int i = 0; i < 256; i++) { int v = partials[i]; partials[i] = s; s += v; }
    }
    __syncthreads();
    const int add = partials[tid];
    for (int i = tid*32; i < tid*32 + 32; i++) hist[i] += add;
    __syncthreads();

#pragma unroll
    for (int k = 0; k < 8; k++) {
        int bb  = myb[k];
        int rnk = hist[bb*256 + tid]++;
        sidx[rnk] = base + k;
    }
}

// ---------------- kernel 3: bucketed attention, tf32 tensor cores --------
// dynamic smem layout (bytes), all strides chosen for conflict-free mma frags:
//   [0,2048)        kiS  : int[512]        window key positions, per round
//   [2048,4096)     cinv : float[512]      1/duplicate-count
//   [4096,21504)    qs   : float[64][68]   Q tile (A frags: stride%32 == 4)
//   [21504,56320)   ks   : float[128][68]  K tile normalized*0.125 (B frags G1)
//                   (aliased by ps float[64][132] and cnt int[2048])
//   [56320,93184)   vs   : float[128][72]  V tile (B frags G2: stride%32 == 8)
#define QS_STR 68
#define KS_STR 68
#define VS_STR 72
#define PS_STR 132
#define ATTN_SMEM 93184

__global__ void __launch_bounds__(256) attn_kernel(const float* __restrict__ query,
                                                   const float* __restrict__ value)
{
    extern __shared__ char smem[];
    int*   kiS  = (int*)  smem;
    float* cinv = (float*)(smem + 2048);
    float* qs   = (float*)(smem + 4096);
    float* ks   = (float*)(smem + 21504);
    float* ps   = ks;                  // alias (after GEMM1)
    int*   cnt  = (int*)  ks;          // alias (phase 0 only)
    float* vs   = (float*)(smem + 56320);

    const int blk = blockIdx.x;
    const int b   = blk >> 5;
    const int n   = blk & 31;
    const int tid = threadIdx.x;
    const int l   = tid & 31;
    const int w   = tid >> 5;
    const int mi  = w & 3;    // m-tile (16 rows)
    const int nh  = w >> 1 >> 1; // n-half

    const int* sidx_b = g_sortidx + b*R*S;
    const int  prev   = (n + 31) & 31;

    // ---- phase 0: window key positions + multiplicity counts (all rounds)
    for (int idx = tid; idx < 512; idx += 256) {
        int r = idx >> 7, j = idx & 127;
        int slot = (j < 64) ? (prev*64 + j) : (n*64 + j - 64);
        kiS[idx] = sidx_b[r*S + slot];
    }
    for (int idx = tid; idx < 2048; idx += 256) cnt[idx] = 0;
    __syncthreads();
    for (int idx = tid; idx < 512; idx += 256) atomicAdd(&cnt[kiS[idx]], 1);
    __syncthreads();
    for (int idx = tid; idx < 512; idx += 256) cinv[idx] = 1.f / (float)cnt[kiS[idx]];
    __syncthreads();

    const float* Q  = query + (size_t)b*S*D;
    const float* V  = value + (size_t)b*S*D;
    const float* qn = g_qninv + b*S;

    for (int r = 0; r < R; r++) {
        const int* ki = kiS + r*128;

        // ---- load tiles (float4 gathers, tf32-rounded into smem) ----
#pragma unroll
        for (int it = 0; it < 8; it++) {
            int idx = it*256 + tid;          // 2048 float4 = 128 rows x 16
            int j   = idx >> 4;
            int d4  = (idx & 15) << 2;
            int kp  = ki[j];
            float4 v = *(const float4*)&Q[(size_t)kp*D + d4];
            float  s = qn[kp] * 0.125f;
            float* kd = &ks[j*KS_STR + d4];
            kd[0] = tff(v.x*s); kd[1] = tff(v.y*s); kd[2] = tff(v.z*s); kd[3] = tff(v.w*s);
            if (j >= 64) {
                float* qd = &qs[(j-64)*QS_STR + d4];
                qd[0] = tff(v.x); qd[1] = tff(v.y); qd[2] = tff(v.z); qd[3] = tff(v.w);
            }
        }
#pragma unroll
        for (int it = 0; it < 8; it++) {
            int idx = it*256 + tid;
            int j   = idx >> 4;
            int d4  = (idx & 15) << 2;
            float4 v = *(const float4*)&V[(size_t)ki[j]*D + d4];
            float* vd = &vs[j*VS_STR + d4];
            vd[0] = tff(v.x); vd[1] = tff(v.y); vd[2] = tff(v.z); vd[3] = tff(v.w);
        }
        __syncthreads();

        // ---- GEMM1: S[64x128] = Q(64x64) . K^T ; warp = 16 rows x 64 cols
        float acc[8][4];
#pragma unroll
        for (int t2 = 0; t2 < 8; t2++)
#pragma unroll
            for (int c = 0; c < 4; c++) acc[t2][c] = 0.f;

        const float* Ab = qs + (mi*16 + (l>>2))*QS_STR + (l&3);
        const float* Bb = ks + (nh*64 + (l>>2))*KS_STR + (l&3);
#pragma unroll
        for (int kk = 0; kk < 8; kk++) {
            unsigned a0 = __float_as_uint(Ab[kk*8]);
            unsigned a1 = __float_as_uint(Ab[8*QS_STR + kk*8]);
            unsigned a2 = __float_as_uint(Ab[kk*8 + 4]);
            unsigned a3 = __float_as_uint(Ab[8*QS_STR + kk*8 + 4]);
#pragma unroll
            for (int nt = 0; nt < 8; nt++) {
                unsigned b0 = __float_as_uint(Bb[nt*8*KS_STR + kk*8]);
                unsigned b1 = __float_as_uint(Bb[nt*8*KS_STR + kk*8 + 4]);
                mma_tf32(acc[nt], a0, a1, a2, a3, b0, b1);
            }
        }
        __syncthreads();   // all warps done reading ks; ps alias safe

        {
            int i0 = mi*16 + (l>>2);
#pragma unroll
            for (int nt = 0; nt < 8; nt++) {
                int c0 = nh*64 + nt*8 + 2*(l&3);
                *(float2*)&ps[i0*PS_STR + c0]     = make_float2(acc[nt][0], acc[nt][1]);
                *(float2*)&ps[(i0+8)*PS_STR + c0] = make_float2(acc[nt][2], acc[nt][3]);
            }
        }
        __syncthreads();

        // ---- softmax + masks + count-div (warp w owns rows 8w..8w+7) ----
        {
            int   kp4[4];
            float ci4[4];
#pragma unroll
            for (int c = 0; c < 4; c++) {
                kp4[c] = ki[l + 32*c];
                ci4[c] = cinv[r*128 + l + 32*c];
            }
#pragma unroll
            for (int rr = 0; rr < 8; rr++) {
                int row  = w*8 + rr;
                int qpos = ki[64 + row];
                float v[4];
                float m = -3.4e38f;
#pragma unroll
                for (int c = 0; c < 4; c++) {
                    float x = ps[row*PS_STR + l + 32*c];
                    int  kp = kp4[c];
                    if      (qpos <  kp) x = -1.0e9f;
                    else if (qpos == kp) x = -1.0e5f;
                    v[c] = x;
                    m = fmaxf(m, x);
                }
#pragma unroll
                for (int off = 16; off; off >>= 1)
                    m = fmaxf(m, __shfl_xor_sync(0xffffffffu, m, off));
                float ssum = 0.f;
#pragma unroll
                for (int c = 0; c < 4; c++) { v[c] = __expf(v[c] - m); ssum += v[c]; }
#pragma unroll
                for (int off = 16; off; off >>= 1)
                    ssum += __shfl_xor_sync(0xffffffffu, ssum, off);
                float inv = 1.f / ssum;
#pragma unroll
                for (int c = 0; c < 4; c++)
                    ps[row*PS_STR + l + 32*c] = tff(v[c] * inv * ci4[c]);
                if (l == 0)
                    g_lse[((size_t)b*S + qpos)*R + r] = m + __logf(ssum);
            }
        }
        __syncthreads();

        // ---- GEMM2: O[64x64] = P(64x128) . V ; warp = 16 rows x 32 cols
        float acc2[4][4];
#pragma unroll
        for (int t2 = 0; t2 < 4; t2++)
#pragma unroll
            for (int c = 0; c < 4; c++) acc2[t2][c] = 0.f;

        const float* Ab2 = ps + (mi*16 + (l>>2))*PS_STR + (l&3);
        const float* Bb2 = vs + (l&3)*VS_STR + nh*32 + (l>>2);
#pragma unroll
        for (int kk = 0; kk < 16; kk++) {
            unsigned a0 = __float_as_uint(Ab2[kk*8]);
            unsigned a1 = __float_as_uint(Ab2[8*PS_STR + kk*8]);
            unsigned a2 = __float_as_uint(Ab2[kk*8 + 4]);
            unsigned a3 = __float_as_uint(Ab2[8*PS_STR + kk*8 + 4]);
#pragma unroll
            for (int nt = 0; nt < 4; nt++) {
                unsigned b0 = __float_as_uint(Bb2[(kk*8)*VS_STR + nt*8]);
                unsigned b1 = __float_as_uint(Bb2[(kk*8 + 4)*VS_STR + nt*8]);
                mma_tf32(acc2[nt], a0, a1, a2, a3, b0, b1);
            }
        }

        {
            int i0 = mi*16 + (l>>2);
            int qpos0 = ki[64 + i0];
            int qpos1 = ki[64 + i0 + 8];
            float* o0 = g_att + (((size_t)b*S + qpos0)*R + r)*D;
            float* o1 = g_att + (((size_t)b*S + qpos1)*R + r)*D;
#pragma unroll
            for (int nt = 0; nt < 4; nt++) {
                int d0 = nh*32 + nt*8 + 2*(l&3);
                *(float2*)&o0[d0] = make_float2(acc2[nt][0], acc2[nt][1]);
                *(float2*)&o1[d0] = make_float2(acc2[nt][2], acc2[nt][3]);
            }
        }
        __syncthreads();   // tiles free for next round
    }
}

// ---------------- kernel 4: per-position round combine -------------------
__global__ void combine_kernel(float* __restrict__ out)
{
    const int tid = threadIdx.x;
    const int d   = tid & 63;
    const int row = (blockIdx.x << 2) + (tid >> 6);   // b*S + t
    const float* lp = g_lse + (size_t)row*R;
    float l0 = lp[0], l1 = lp[1], l2 = lp[2], l3 = lp[3];
    float m  = fmaxf(fmaxf(l0, l1), fmaxf(l2, l3));
    float w0 = __expf(l0 - m), w1 = __expf(l1 - m);
    float w2 = __expf(l2 - m), w3 = __expf(l3 - m);
    float inv = 1.f / (w0 + w1 + w2 + w3);
    const float* a = g_att + (size_t)row*R*D;
    out[(size_t)row*D + d] =
        (a[0*D + d]*w0 + a[1*D + d]*w1 + a[2*D + d]*w2 + a[3*D + d]*w3) * inv;
}

// ---------------- launch --------------------------------------------------
extern "C" void kernel_launch(void* const* d_in, const int* in_sizes, int n_in,
                              void* d_out, int out_size)
{
    const float* query = (const float*)d_in[0];
    const float* value = (const float*)d_in[1];
    const float* randm = (const float*)d_in[2];
    float* out = (float*)d_out;

    cudaFuncSetAttribute(attn_kernel,
                         cudaFuncAttributeMaxDynamicSharedMemorySize, ATTN_SMEM);

    hash_kernel<<<dim3(S/128, B), 128>>>(query, randm);
    sort_kernel<<<B*R, 256>>>();
    attn_kernel<<<B*NB, 256, ATTN_SMEM>>>(query, value);
    combine_kernel<<<(B*S)/4, 256>>>(out);
}

// round 3
// speedup vs baseline: 4.6946x; 1.6648x over previous
#include <cuda_runtime.h>
#include <cuda_fp16.h>
#include <math.h>

#define B  32
#define S  2048
#define D  64
#define R  4
#define NB 32

// ---------------- scratch (device globals; no allocation) ----------------
__device__ int    g_bucket[B*R*S];            // 1 MB
__device__ int    g_sortidx[B*R*S];           // 1 MB
__device__ float  g_qninv[B*S];               // 256 KB
__device__ __half g_att[(size_t)B*S*R*D];     // 32 MB  [b][t][r][d]
__device__ float  g_lse[B*S*R];               // 1 MB   [b][t][r]

// ---------------- mma / cp.async helpers ---------------------------------
__device__ __forceinline__ void mma_tf32(float* c,
                                         unsigned a0, unsigned a1, unsigned a2, unsigned a3,
                                         unsigned b0, unsigned b1)
{
    asm volatile(
        "mma.sync.aligned.m16n8k8.row.col.f32.tf32.tf32.f32 "
        "{%0,%1,%2,%3}, {%4,%5,%6,%7}, {%8,%9}, {%0,%1,%2,%3};"
        : "+f"(c[0]), "+f"(c[1]), "+f"(c[2]), "+f"(c[3])
        : "r"(a0), "r"(a1), "r"(a2), "r"(a3), "r"(b0), "r"(b1));
}

__device__ __forceinline__ void cpa16(unsigned dst, const float* src) {
    asm volatile("cp.async.cg.shared.global [%0], [%1], 16;" :: "r"(dst), "l"(src));
}

// ---------------- kernel 1: hash projection + bucket + key norm ----------
#define HASH_SMEM (128*65*4 + 64*64*4)   // sQ[128][65] + sR[64][64] = 49664 B

__global__ void __launch_bounds__(128) hash_kernel(const float* __restrict__ query,
                                                   const float* __restrict__ randm)
{
    extern __shared__ float hs[];
    float* sQ = hs;            // [128][65] (pad: conflict-free row reads)
    float* sR = hs + 128*65;   // [64][64]  d-major, rk = r*16+k
    const int b   = blockIdx.y;
    const int tid = threadIdx.x;

    for (int i = tid; i < 4096; i += 128) sR[i] = randm[b*4096 + i];
    const size_t qbase = ((size_t)b*S + (size_t)blockIdx.x*128)*D;
    for (int i = tid; i < 2048; i += 128) {           // coalesced float4
        float4 v = *(const float4*)&query[qbase + (size_t)i*4];
        int row = i >> 4, d4 = (i & 15) << 2;
        float* p = &sQ[row*65 + d4];
        p[0] = v.x; p[1] = v.y; p[2] = v.z; p[3] = v.w;
    }
    __syncthreads();

    const int t = blockIdx.x*128 + tid;
    const float* q = &sQ[tid*65];

    float acc[64];
#pragma unroll
    for (int i = 0; i < 64; i++) acc[i] = 0.f;
    float nrm = 0.f;
    for (int d = 0; d < D; d++) {
        float qd = q[d];
        nrm += qd*qd;
        const float* rr = &sR[d*64];
#pragma unroll
        for (int i = 0; i < 64; i++) acc[i] += qd * rr[i];
    }
    g_qninv[b*S + t] = rsqrtf(fmaxf(nrm, 1e-12f));

#pragma unroll
    for (int r = 0; r < R; r++) {
        float bv = acc[r*16];
        int   bi = 0;
#pragma unroll
        for (int k = 1; k < 16; k++) {
            float v = acc[r*16 + k];
            if (v > bv) { bv = v; bi = k; }
        }
#pragma unroll
        for (int k = 0; k < 16; k++) {
            float v = -acc[r*16 + k];
            if (v > bv) { bv = v; bi = 16 + k; }
        }
        g_bucket[(b*R + r)*S + t] = bi;
    }
}

// ---------------- kernel 2: stable counting sort per (b, r) --------------
__global__ void sort_kernel()
{
    __shared__ int hist[NB*256];   // bucket-major, thread-minor
    __shared__ int partials[256];
    __shared__ int wtot[8];
    const int br  = blockIdx.x;
    const int tid = threadIdx.x;
    const int* bk = g_bucket  + br*S;
    int*     sidx = g_sortidx + br*S;

    for (int i = tid; i < NB*256; i += 256) hist[i] = 0;
    __syncthreads();

    const int base = tid*8;
    int myb[8];
#pragma unroll
    for (int k = 0; k < 8; k++) { myb[k] = bk[base + k]; hist[myb[k]*256 + tid]++; }
    __syncthreads();

    // exclusive scan over 8192 entries in index order (stable)
    int run = 0;
    for (int i = tid*32; i < tid*32 + 32; i++) { int v = hist[i]; hist[i] = run; run += v; }
    // parallel exclusive scan of per-thread totals
    const int lane = tid & 31, wid = tid >> 5;
    int x = run;
#pragma unroll
    for (int off = 1; off < 32; off <<= 1) {
        int nv = __shfl_up_sync(0xffffffffu, x, off);
        if (lane >= off) x += nv;
    }
    if (lane == 31) wtot[wid] = x;
    __syncthreads();
    if (tid < 8) {
        int y = wtot[tid], z = y;
#pragma unroll
        for (int off = 1; off < 8; off <<= 1) {
            int nv = __shfl_up_sync(0x000000ffu, z, off);
            if (tid >= off) z += nv;
        }
        wtot[tid] = z - y;    // exclusive warp offsets
    }
    __syncthreads();
    const int add = (x - run) + wtot[wid];
    for (int i = tid*32; i < tid*32 + 32; i++) hist[i] += add;
    __syncthreads();

#pragma unroll
    for (int k = 0; k < 8; k++) {
        int bb  = myb[k];
        int rnk = hist[bb*256 + tid]++;
        sidx[rnk] = base + k;
    }
}

// ---------------- kernel 3: bucketed attention, tf32 tensor cores --------
// smem layout (bytes):
//   [0,2048)        kiS   : int[512]         window key positions, per round
//   [2048,4096)     cinvS : float[512]       1/duplicate-count
//   [4096,6144)     scS   : float[512]       per-key qn*0.125 scale
//   [6144,7168)     statS : float2[64][2]    per-row (m,s) per warp-half
//   [7168,41984)    ksA   : float[128][68]   K window tile (rows 64.. = Q tile)
//                   (ps float[64][132] aliases ksA after GEMM1; cnt in vs)
//   [41984,78848)   vs    : float[128][72]   V tile
#define KS_STR 68
#define VS_STR 72
#define PS_STR 132
#define OFF_KI    0
#define OFF_CINV  2048
#define OFF_SC    4096
#define OFF_STATS 6144
#define OFF_KS    7168
#define OFF_PS    7168
#define OFF_VS    41984
#define ATTN_SMEM 78848

__global__ void __launch_bounds__(256) attn_kernel(const float* __restrict__ query,
                                                   const float* __restrict__ value)
{
    extern __shared__ char smem[];
    int*    kiS   = (int*)   (smem + OFF_KI);
    float*  cinvS = (float*) (smem + OFF_CINV);
    float*  scS   = (float*) (smem + OFF_SC);
    float2* statS = (float2*)(smem + OFF_STATS);
    float*  ksA   = (float*) (smem + OFF_KS);
    float*  ps    = (float*) (smem + OFF_PS);   // alias (after GEMM1)
    float*  vs    = (float*) (smem + OFF_VS);
    int*    cnt   = (int*)   (smem + OFF_VS);   // alias (phase 0 only)

    const int blk = blockIdx.x;
    const int b   = blk >> 5;
    const int n   = blk & 31;
    const int tid = threadIdx.x;
    const int l   = tid & 31;
    const int w   = tid >> 5;
    const int mi  = w & 3;     // m-tile (16 rows)
    const int nh  = w >> 2;    // n-half (64 cols)

    const int* sidx_b = g_sortidx + b*R*S;
    const int  prev   = (n + 31) & 31;
    const float* qn   = g_qninv + b*S;

    // ---- phase 0: window key positions + multiplicity + scales ----
    for (int idx = tid; idx < 512; idx += 256) {
        int r = idx >> 7, j = idx & 127;
        int slot = (j < 64) ? (prev*64 + j) : (n*64 + j - 64);
        kiS[idx] = sidx_b[r*S + slot];
    }
    for (int idx = tid; idx < 2048; idx += 256) cnt[idx] = 0;
    __syncthreads();
    for (int idx = tid; idx < 512; idx += 256) atomicAdd(&cnt[kiS[idx]], 1);
    __syncthreads();
    for (int idx = tid; idx < 512; idx += 256) {
        int kp = kiS[idx];
        cinvS[idx] = 1.f / (float)cnt[kp];
        scS[idx]   = qn[kp] * 0.125f;
    }
    __syncthreads();

    const float* Q = query + (size_t)b*S*D;
    const float* V = value + (size_t)b*S*D;

    const unsigned ks_s = (unsigned)__cvta_generic_to_shared(ksA);
    const unsigned vs_s = (unsigned)__cvta_generic_to_shared(vs);
    const int i0 = mi*16 + (l>>2);

    for (int r = 0; r < R; r++) {
        const int* ki = kiS + r*128;

        // ---- load tiles: raw fp32 via cp.async (mma truncates to tf32) ----
#pragma unroll
        for (int it = 0; it < 16; it++) {
            int idx = it*256 + tid;             // 4096 x 16B
            int row = idx >> 4, c4 = (idx & 15) << 2;
            if (row < 128) {
                cpa16(ks_s + (unsigned)(row*KS_STR + c4)*4, &Q[(size_t)ki[row]*D + c4]);
            } else {
                int j = row - 128;
                cpa16(vs_s + (unsigned)(j*VS_STR + c4)*4, &V[(size_t)ki[j]*D + c4]);
            }
        }
        asm volatile("cp.async.commit_group;");
        asm volatile("cp.async.wait_group 0;");
        __syncthreads();

        // ---- GEMM1: S[64x128] = Q(rows 64..127 of ksA) . K^T ----
        float acc[8][4];
#pragma unroll
        for (int t2 = 0; t2 < 8; t2++)
#pragma unroll
            for (int c = 0; c < 4; c++) acc[t2][c] = 0.f;

        const float* Ab = ksA + (64 + i0)*KS_STR + (l&3);
        const float* Bb = ksA + (nh*64 + (l>>2))*KS_STR + (l&3);
#pragma unroll
        for (int kk = 0; kk < 8; kk++) {
            unsigned a0 = __float_as_uint(Ab[kk*8]);
            unsigned a1 = __float_as_uint(Ab[8*KS_STR + kk*8]);
            unsigned a2 = __float_as_uint(Ab[kk*8 + 4]);
            unsigned a3 = __float_as_uint(Ab[8*KS_STR + kk*8 + 4]);
#pragma unroll
            for (int nt = 0; nt < 8; nt++) {
                unsigned b0 = __float_as_uint(Bb[nt*8*KS_STR + kk*8]);
                unsigned b1 = __float_as_uint(Bb[nt*8*KS_STR + kk*8 + 4]);
                mma_tf32(acc[nt], a0, a1, a2, a3, b0, b1);
            }
        }

        // ---- in-register scale + masks + local softmax stats ----
        const int qpos0 = ki[64 + i0];
        const int qpos1 = ki[64 + i0 + 8];
        float m0 = -3.4e38f, m1 = -3.4e38f;
#pragma unroll
        for (int nt = 0; nt < 8; nt++) {
#pragma unroll
            for (int e = 0; e < 2; e++) {
                int col = nh*64 + nt*8 + 2*(l&3) + e;
                int kp  = ki[col];
                float sc = scS[r*128 + col];
                float x = acc[nt][e] * sc;
                if      (qpos0 <  kp) x = -1.0e9f;
                else if (qpos0 == kp) x = -1.0e5f;
                acc[nt][e] = x; m0 = fmaxf(m0, x);
                float y = acc[nt][2+e] * sc;
                if      (qpos1 <  kp) y = -1.0e9f;
                else if (qpos1 == kp) y = -1.0e5f;
                acc[nt][2+e] = y; m1 = fmaxf(m1, y);
            }
        }
        m0 = fmaxf(m0, __shfl_xor_sync(0xffffffffu, m0, 1));
        m0 = fmaxf(m0, __shfl_xor_sync(0xffffffffu, m0, 2));
        m1 = fmaxf(m1, __shfl_xor_sync(0xffffffffu, m1, 1));
        m1 = fmaxf(m1, __shfl_xor_sync(0xffffffffu, m1, 2));
        float s0 = 0.f, s1 = 0.f;
#pragma unroll
        for (int nt = 0; nt < 8; nt++)
#pragma unroll
            for (int e = 0; e < 2; e++) {
                float ex = __expf(acc[nt][e]   - m0); acc[nt][e]   = ex; s0 += ex;
                float ey = __expf(acc[nt][2+e] - m1); acc[nt][2+e] = ey; s1 += ey;
            }
        s0 += __shfl_xor_sync(0xffffffffu, s0, 1);
        s0 += __shfl_xor_sync(0xffffffffu, s0, 2);
        s1 += __shfl_xor_sync(0xffffffffu, s1, 1);
        s1 += __shfl_xor_sync(0xffffffffu, s1, 2);
        if ((l & 3) == 0) {
            statS[i0*2 + nh]       = make_float2(m0, s0);
            statS[(i0 + 8)*2 + nh] = make_float2(m1, s1);
        }
        __syncthreads();   // stats visible; all GEMM1 ksA reads done (ps alias safe)

        float2 ha = statS[i0*2],       hb = statS[i0*2 + 1];
        float M0 = fmaxf(ha.x, hb.x);
        float S0 = ha.y*__expf(ha.x - M0) + hb.y*__expf(hb.x - M0);
        float2 hc = statS[(i0+8)*2],   hd = statS[(i0+8)*2 + 1];
        float M1 = fmaxf(hc.x, hd.x);
        float S1 = hc.y*__expf(hc.x - M1) + hd.y*__expf(hd.x - M1);
        const float f0 = __expf(m0 - M0) / S0;
        const float f1 = __expf(m1 - M1) / S1;

#pragma unroll
        for (int nt = 0; nt < 8; nt++) {
            int col0 = nh*64 + nt*8 + 2*(l&3);
            float ci0 = cinvS[r*128 + col0], ci1 = cinvS[r*128 + col0 + 1];
            *(float2*)&ps[i0*PS_STR + col0] =
                make_float2(acc[nt][0]*f0*ci0, acc[nt][1]*f0*ci1);
            *(float2*)&ps[(i0+8)*PS_STR + col0] =
                make_float2(acc[nt][2]*f1*ci0, acc[nt][3]*f1*ci1);
        }
        if (((l & 3) == 0) && nh == 0) {
            g_lse[((size_t)b*S + qpos0)*R + r] = M0 + __logf(S0);
            g_lse[((size_t)b*S + qpos1)*R + r] = M1 + __logf(S1);
        }
        __syncthreads();

        // ---- GEMM2: O[64x64] = P(64x128) . V ----
        float acc2[4][4];
#pragma unroll
        for (int t2 = 0; t2 < 4; t2++)
#pragma unroll
            for (int c = 0; c < 4; c++) acc2[t2][c] = 0.f;

        const float* Ab2 = ps + i0*PS_STR + (l&3);
        const float* Bb2 = vs + (l&3)*VS_STR + nh*32 + (l>>2);
#pragma unroll
        for (int kk = 0; kk < 16; kk++) {
            unsigned a0 = __float_as_uint(Ab2[kk*8]);
            unsigned a1 = __float_as_uint(Ab2[8*PS_STR + kk*8]);
            unsigned a2 = __float_as_uint(Ab2[kk*8 + 4]);
            unsigned a3 = __float_as_uint(Ab2[8*PS_STR + kk*8 + 4]);
#pragma unroll
            for (int nt = 0; nt < 4; nt++) {
                unsigned b0 = __float_as_uint(Bb2[(kk*8)*VS_STR + nt*8]);
                unsigned b1 = __float_as_uint(Bb2[(kk*8 + 4)*VS_STR + nt*8]);
                mma_tf32(acc2[nt], a0, a1, a2, a3, b0, b1);
            }
        }

        __half* o0 = g_att + (((size_t)b*S + qpos0)*R + r)*D;
        __half* o1 = g_att + (((size_t)b*S + qpos1)*R + r)*D;
#pragma unroll
        for (int nt = 0; nt < 4; nt++) {
            int d0 = nh*32 + nt*8 + 2*(l&3);
            *(__half2*)&o0[d0] = __floats2half2_rn(acc2[nt][0], acc2[nt][1]);
            *(__half2*)&o1[d0] = __floats2half2_rn(acc2[nt][2], acc2[nt][3]);
        }
        __syncthreads();   // ps/vs free for next round's cp.async
    }
}

// ---------------- kernel 4: per-position round combine (fp16 att) --------
__global__ void combine_kernel(float* __restrict__ out)
{
    const int tid = threadIdx.x;
    const int d2  = tid & 31;                       // half2 index (2 dims)
    const int row = blockIdx.x*8 + (tid >> 5);      // b*S + t
    const float* lp = g_lse + (size_t)row*R;
    float l0 = lp[0], l1 = lp[1], l2 = lp[2], l3 = lp[3];
    float m  = fmaxf(fmaxf(l0, l1), fmaxf(l2, l3));
    float w0 = __expf(l0 - m), w1 = __expf(l1 - m);
    float w2 = __expf(l2 - m), w3 = __expf(l3 - m);
    float inv = 1.f / (w0 + w1 + w2 + w3);
    const __half2* a = (const __half2*)g_att + (size_t)row*R*(D/2);
    float2 a0 = __half22float2(a[0*(D/2) + d2]);
    float2 a1 = __half22float2(a[1*(D/2) + d2]);
    float2 a2 = __half22float2(a[2*(D/2) + d2]);
    float2 a3 = __half22float2(a[3*(D/2) + d2]);
    float2 res;
    res.x = (a0.x*w0 + a1.x*w1 + a2.x*w2 + a3.x*w3) * inv;
    res.y = (a0.y*w0 + a1.y*w1 + a2.y*w2 + a3.y*w3) * inv;
    *(float2*)&out[(size_t)row*D + d2*2] = res;
}

// ---------------- launch --------------------------------------------------
extern "C" void kernel_launch(void* const* d_in, const int* in_sizes, int n_in,
                              void* d_out, int out_size)
{
    const float* query = (const float*)d_in[0];
    const float* value = (const float*)d_in[1];
    const float* randm = (const float*)d_in[2];
    float* out = (float*)d_out;

    cudaFuncSetAttribute(hash_kernel,
                         cudaFuncAttributeMaxDynamicSharedMemorySize, HASH_SMEM);
    cudaFuncSetAttribute(attn_kernel,
                         cudaFuncAttributeMaxDynamicSharedMemorySize, ATTN_SMEM);

    hash_kernel<<<dim3(S/128, B), 128, HASH_SMEM>>>(query, randm);
    sort_kernel<<<B*R, 256>>>();
    attn_kernel<<<B*NB, 256, ATTN_SMEM>>>(query, value);
    combine_kernel<<<(B*S)/8, 256>>>(out);
}